// round 6
// baseline (speedup 1.0000x reference)
#include <cuda_runtime.h>
#include <math.h>

#define TPB 448
#define G 4
typedef unsigned long long ull;
constexpr int S_ = 500;

// ---------------- device scratch tables ----------------
__device__ float g_tk[2500];
__device__ float g_attn[1001 * 52];
__device__ float g_c1[1001 * 100];
__device__ float g_ve[4004 * 200];
__device__ float g_ea[(size_t)4004 * 400];
__device__ float g_wo2[400];   // Wo@W2 [4][100]
__device__ float g_bo2[4];     // Wo@b2+bo
__device__ float g_w2m[100];   // colmean(W2)
__device__ float g_b2m[1];     // mean(b2)

// ---------------- f32x2 helpers ----------------
#define FMA2(d, a, b, c) \
    asm("fma.rn.f32x2 %0, %1, %2, %3;" : "=l"(d) : "l"(a), "l"(b), "l"(c))
__device__ __forceinline__ ull PK(float x, float y) {
    ull u;
    asm("mov.b64 %0, {%1, %2};" : "=l"(u) : "r"(__float_as_uint(x)), "r"(__float_as_uint(y)));
    return u;
}
__device__ __forceinline__ float HADD(ull u) {
    unsigned lo, hi;
    asm("mov.b64 {%0, %1}, %2;" : "=r"(lo), "=r"(hi) : "l"(u));
    return __uint_as_float(lo) + __uint_as_float(hi);
}
__device__ __forceinline__ void cp16(float* dst, const float* src) {
    unsigned d = (unsigned)__cvta_generic_to_shared(dst);
    asm volatile("cp.async.ca.shared.global [%0], [%1], 16;\n" :: "r"(d), "l"(src));
}

// ---------------- fused prep A ----------------
__global__ void prepA(const float* __restrict__ Wv, const float* __restrict__ bv,
                      const float* __restrict__ qet, const float* __restrict__ W1,
                      const float* __restrict__ b1,
                      const float* __restrict__ km, const float* __restrict__ Wk,
                      const float* __restrict__ bk,
                      const float* __restrict__ W2, const float* __restrict__ b2,
                      const float* __restrict__ Wo, const float* __restrict__ bo) {
    int b = blockIdx.x, tid = threadIdx.x;
    if (b < 3129) {
        int idx = b * 256 + tid;
        if (idx < 4004 * 200) {
            int i = idx / 200, v = idx % 200;
            int q = i >> 2, r = i & 3;
            float acc = bv[v];
            if (q > 0) {
#pragma unroll
                for (int c = 0; c < 4; c++) {
                    float w = 1.0f - fabsf((float)(c - r)) * (1.0f / 3.0f);
                    if (w > 0.0f) acc = fmaf(w, Wv[v * 4000 + c * 1000 + q - 1], acc);
                }
            }
            g_ve[idx] = acc;
        }
    } else if (b < 3521) {
        int idx = (b - 3129) * 256 + tid;
        if (idx < 1001 * 100) {
            int q = idx / 100, j = idx % 100;
            float a = b1[j];
            const float* w = W1 + j * 250 + 200;
            const float* e = qet + q * 50;
            for (int k = 0; k < 50; k++) a = fmaf(w[k], e[k], a);
            g_c1[idx] = a;
        }
    } else if (b < 3531) {
        int i = (b - 3521) * 256 + tid;
        if (i < 2500) {
            int m = i / 50, k = i % 50;
            float a = bk[m];
            for (int l = 0; l < 50; l++) a = fmaf(km[l * 50 + k], Wk[m * 50 + l], a);
            g_tk[i] = a;
        }
    } else {
        int i = (b - 3531) * 256 + tid;
        if (i < 400) {
            int c = i / 100, k = i % 100;
            float a = 0.f;
            for (int f = 0; f < 50; f++) a = fmaf(Wo[c * 50 + f], W2[f * 100 + k], a);
            g_wo2[i] = a;
        } else if (i < 500) {
            int k = i - 400;
            float a = 0.f;
            for (int f = 0; f < 50; f++) a += W2[f * 100 + k];
            g_w2m[k] = a * (1.f / 50.f);
        } else if (i < 504) {
            int c = i - 500;
            float a = bo[c];
            for (int f = 0; f < 50; f++) a = fmaf(Wo[c * 50 + f], b2[f], a);
            g_bo2[c] = a;
        } else if (i == 504) {
            float a = 0.f;
            for (int f = 0; f < 50; f++) a += b2[f];
            g_b2m[0] = a * (1.f / 50.f);
        }
    }
}

// ---------------- prep B: attention ----------------
__global__ void prepB(const float* __restrict__ qet, const float* __restrict__ Wq,
                      const float* __restrict__ bq) {
    __shared__ float qe[50], qu[50], lg[50], red[2];
    int q = blockIdx.x, tid = threadIdx.x;
    if (tid < 50) qe[tid] = qet[q * 50 + tid];
    __syncthreads();
    if (tid < 50) {
        float a = bq[tid];
        for (int l = 0; l < 50; l++) a = fmaf(Wq[tid * 50 + l], qe[l], a);
        qu[tid] = tanhf(a);
    }
    __syncthreads();
    if (tid < 50) {
        float a = 0.f;
        for (int k = 0; k < 50; k++) a = fmaf(g_tk[tid * 50 + k], qu[k], a);
        lg[tid] = a;
    }
    __syncthreads();
    if (tid == 0) {
        float mx = -1e30f;
        for (int m = 0; m < 50; m++) mx = fmaxf(mx, lg[m]);
        float s = 0.f;
        for (int m = 0; m < 50; m++) s += expf(lg[m] - mx);
        red[0] = mx; red[1] = 1.f / s;
    }
    __syncthreads();
    if (tid < 52) g_attn[q * 52 + tid] = (tid < 50) ? expf(lg[tid] - red[0]) * red[1] : 0.f;
}

// ---------------- prep C: erase/add GEMM ----------------
__global__ void prepC(const float* __restrict__ We, const float* __restrict__ be,
                      const float* __restrict__ Wa, const float* __restrict__ ba) {
    __shared__ float As[16][64];
    __shared__ float Bs[16][64];
    int i0 = blockIdx.x * 64, j0 = blockIdx.y * 64;
    int tid = threadIdx.x;
    int ty = tid >> 4, tx = tid & 15;
    float acc[4][4] = {};
    for (int kb = 0; kb < 200; kb += 16) {
        for (int l = tid; l < 1024; l += 256) {
            int r = l >> 4, c = l & 15;
            int gi = i0 + r, gk = kb + c;
            As[c][r] = (gi < 4004 && gk < 200) ? g_ve[gi * 200 + gk] : 0.f;
            int gj = j0 + r;
            float bval = 0.f;
            if (gj < 400 && gk < 200)
                bval = (gj < 200) ? We[gj * 200 + gk] : Wa[(gj - 200) * 200 + gk];
            Bs[c][r] = bval;
        }
        __syncthreads();
#pragma unroll
        for (int k = 0; k < 16; k++) {
            float a[4], b[4];
#pragma unroll
            for (int u = 0; u < 4; u++) a[u] = As[k][ty * 4 + u];
#pragma unroll
            for (int u = 0; u < 4; u++) b[u] = Bs[k][tx * 4 + u];
#pragma unroll
            for (int u = 0; u < 4; u++)
#pragma unroll
                for (int v = 0; v < 4; v++) acc[u][v] = fmaf(a[u], b[v], acc[u][v]);
        }
        __syncthreads();
    }
#pragma unroll
    for (int u = 0; u < 4; u++) {
        int gi = i0 + ty * 4 + u;
        if (gi >= 4004) break;
#pragma unroll
        for (int v = 0; v < 4; v++) {
            int gj = j0 + tx * 4 + v;
            if (gj >= 400) continue;
            float x = acc[u][v] + ((gj < 200) ? be[gj] : ba[gj - 200]);
            g_ea[(size_t)gi * 400 + gj] = (gj < 200) ? (1.0f / (1.0f + expf(-x))) : tanhf(x);
        }
    }
}

// ---------------- main kernel ----------------
constexpr int O_TBL = 0;        // 2 x 2208
constexpr int O_QS  = 4416;     // 2000 int
constexpr int O_RS  = 6416;     // 2000 int
constexpr int O_H   = 8416;     // [g][kq][52] = 832
constexpr int O_H1  = 9248;     // 2 x 400
constexpr int O_WO2 = 10048;    // 400
constexpr int O_BO2 = 10448;    // 4
constexpr int O_W2M = 10452;    // 100
constexpr int O_B2M = 10552;    // 1 (+3 pad)
constexpr int O_W1Q = 10556;    // 20800
constexpr int O_VMS = 31356;    // [4 g][18 m][200 v] = 14400
constexpr int SMEM_F = 45756;   // 183,024 B

__device__ __forceinline__ void prefetch_tbl(float* dst, const int* qs, const int* rs,
                                             int t1, int i0, int stride) {
    for (int i = i0; i < 552; i += stride) {
        if (i < 400) {
            int g = i / 100, j = i % 100;
            int q = qs[g * S_ + t1], r = rs[g * S_ + t1];
            cp16(dst + g * 400 + j * 4, g_ea + (size_t)(q * 4 + r) * 400 + j * 4);
        } else if (i < 452) {
            int k = i - 400, g = k / 13, j = k % 13;
            cp16(dst + 1600 + g * 52 + j * 4, g_attn + qs[g * S_ + t1] * 52 + j * 4);
        } else {
            int k = i - 452, g = k / 25, j = k % 25;
            cp16(dst + 1808 + g * 100 + j * 4, g_c1 + qs[g * S_ + t1] * 100 + j * 4);
        }
    }
}

#define S1_STEP(X, RACC) do {                   \
        ull at2 = PK(av[d], av[d]); ull tt;     \
        FMA2(RACC, at2, (X), RACC);             \
        FMA2(tt, en, (X), ad);                  \
        FMA2((X), at2, tt, (X));                \
    } while (0)

__global__ void __launch_bounds__(TPB, 1)
akvmn_main(const int* __restrict__ questions, const int* __restrict__ responses,
           const float* __restrict__ ivm,
           const float* __restrict__ W1, const float* __restrict__ W2,
           const float* __restrict__ b2,
           float* __restrict__ outF, float* __restrict__ outM,
           float* __restrict__ outL, float* __restrict__ outP) {
    extern __shared__ float sm[];
    int* qs = (int*)(sm + O_QS);
    int* rs = (int*)(sm + O_RS);

    const int tid = threadIdx.x;
    const int b0 = blockIdx.x * G;
    const int g = (tid < 400) ? tid / 100 : 0;
    const int p = (tid < 400) ? tid % 100 : 0;

    // ---- setup ----
    for (int i = tid; i < 2000; i += TPB) {
        qs[i] = questions[b0 * S_ + i];
        rs[i] = responses[b0 * S_ + i];
    }
    for (int i = tid; i < 5200; i += TPB) {
        int kk4 = i / 100, row = i % 100;
        int kq = kk4 / 13, j = kk4 % 13;
        float4 w;
        float* wp = (float*)&w;
#pragma unroll
        for (int d = 0; d < 4; d++) {
            int kin = j * 4 + d;
            wp[d] = (kin < 50) ? W1[row * 250 + kq * 50 + kin] : 0.f;
        }
        *(float4*)&sm[O_W1Q + i * 4] = w;
    }
    // Vm smem half: m 32..49 (18 rows)
    for (int i = tid; i < 3600; i += TPB) {
        int mm = i / 200, v = i % 200;
        float val = ivm[(32 + mm) * 200 + v];
#pragma unroll
        for (int gg = 0; gg < G; gg++) sm[O_VMS + gg * 3600 + i] = val;
    }
    for (int i = tid; i < 832; i += TPB) sm[O_H + i] = 0.f;
    for (int i = tid; i < 400; i += TPB) sm[O_WO2 + i] = g_wo2[i];
    if (tid < 4) sm[O_BO2 + tid] = g_bo2[tid];
    for (int i = tid; i < 100; i += TPB) sm[O_W2M + i] = g_w2m[i];
    if (tid == 0) sm[O_B2M] = g_b2m[0];

    // Vm register half: m 0..31 (64 regs)
    ull vmr[32];
#pragma unroll
    for (int m = 0; m < 32; m++)
        vmr[m] = (tid < 400) ? *(const ull*)(ivm + m * 200 + 2 * p) : 0ull;

    __syncthreads();
    if (tid >= 400) {
        prefetch_tbl(sm + O_TBL, qs, rs, 0, tid - 400, TPB - 400);
        asm volatile("cp.async.commit_group;\n" ::: "memory");
    }

    for (int t = 0; t <= S_; t++) {
        if (tid >= 400)
            asm volatile("cp.async.wait_group 0;\n" ::: "memory");
        __syncthreads();   // sync A

        // ======== stage 1: S1(t) | prefetch(t+1) ========
        if (tid < 400 && t < S_) {
            const float* tc = sm + O_TBL + (t & 1) * 2208;
            float2 e2 = *(const float2*)(tc + g * 400 + 2 * p);
            float2 a2f = *(const float2*)(tc + g * 400 + 200 + 2 * p);
            ull en = PK(-e2.x, -e2.y), ad = PK(a2f.x, a2f.y);
            const float* at = tc + 1600 + g * 52;
            ull r2a = 0ull, r2b = 0ull;
#pragma unroll
            for (int c = 0; c < 8; c++) {          // m 0..31 in registers
                float4 a4 = *(const float4*)(at + c * 4);
                float av[4] = {a4.x, a4.y, a4.z, a4.w};
#pragma unroll
                for (int d = 0; d < 4; d++) {
                    if (d & 1) S1_STEP(vmr[c * 4 + d], r2b);
                    else       S1_STEP(vmr[c * 4 + d], r2a);
                }
            }
            float* vp = sm + O_VMS + g * 3600 + 2 * p;
#pragma unroll
            for (int c = 8; c < 12; c++) {         // m 32..47 in smem
                float4 a4 = *(const float4*)(at + c * 4);
                float av[4] = {a4.x, a4.y, a4.z, a4.w};
#pragma unroll
                for (int d = 0; d < 4; d++) {
                    int mm = c * 4 + d - 32;
                    ull x = *(ull*)(vp + mm * 200);
                    if (d & 1) S1_STEP(x, r2b);
                    else       S1_STEP(x, r2a);
                    *(ull*)(vp + mm * 200) = x;
                }
            }
            {                                       // m 48,49
                float4 a4 = *(const float4*)(at + 48);
                float av[4] = {a4.x, a4.y, a4.z, a4.w};
#pragma unroll
                for (int d = 0; d < 2; d++) {
                    int mm = 16 + d;
                    ull x = *(ull*)(vp + mm * 200);
                    if (d & 1) S1_STEP(x, r2b);
                    else       S1_STEP(x, r2a);
                    *(ull*)(vp + mm * 200) = x;
                }
            }
            // packed lane-wise add of the two accumulators
            {
                ull one2 = PK(1.0f, 1.0f);
                ull r2;
                FMA2(r2, r2b, one2, r2a);
                int kq = (2 * p) / 50;
                *(ull*)(sm + O_H + (g * 4 + kq) * 52 + (2 * p - kq * 50)) = r2;
            }
        } else if (tid >= 400) {
            if (t + 1 < S_)
                prefetch_tbl(sm + O_TBL + ((t + 1) & 1) * 2208, qs, rs, t + 1,
                             tid - 400, TPB - 400);
            asm volatile("cp.async.commit_group;\n" ::: "memory");
        }
        __syncthreads();   // sync B

        // ======== stage 2: S2(t) | S4(t-1) on warp 13 ========
        if (tid < 400 && t < S_) {
            int row = tid >> 2, kq = tid & 3;
            ull acc[G] = {};
            const ulonglong2* wb = (const ulonglong2*)(sm + O_W1Q) + kq * 13 * 100 + row;
#pragma unroll
            for (int j = 0; j < 13; j++) {
                ulonglong2 w = wb[j * 100];
#pragma unroll
                for (int gg = 0; gg < G; gg++) {
                    ulonglong2 h = *(const ulonglong2*)(sm + O_H + (gg * 4 + kq) * 52 + j * 4);
                    FMA2(acc[gg], w.x, h.x, acc[gg]);
                    FMA2(acc[gg], w.y, h.y, acc[gg]);
                }
            }
            unsigned msk = __activemask();
            float s[G];
#pragma unroll
            for (int gg = 0; gg < G; gg++) {
                s[gg] = HADD(acc[gg]);
                s[gg] += __shfl_xor_sync(msk, s[gg], 1);
                s[gg] += __shfl_xor_sync(msk, s[gg], 2);
            }
            const float* c1c = sm + O_TBL + (t & 1) * 2208 + 1808;
            sm[O_H1 + (t & 1) * 400 + kq * 100 + row] =
                fmaxf(s[kq] + c1c[kq * 100 + row], 0.f);
        } else if (t >= 1 && tid >= 416 && tid < 448) {
            int lane = tid - 416;
            int tt = t - 1;
            const float* h1o = sm + O_H1 + ((t + 1) & 1) * 400;
            if (lane < 16) {
                int gg = lane >> 2, c = lane & 3;
                ull acc = 0ull;
#pragma unroll
                for (int k2 = 0; k2 < 50; k2++)
                    FMA2(acc, *(const ull*)(sm + O_WO2 + c * 100 + 2 * k2),
                         *(const ull*)(h1o + gg * 100 + 2 * k2), acc);
                float lg = HADD(acc) + sm[O_BO2 + c];
                float mx = fmaxf(lg, __shfl_xor_sync(0xffffu, lg, 1));
                mx = fmaxf(mx, __shfl_xor_sync(0xffffu, mx, 2));
                float e = expf(lg - mx);
                float se = e + __shfl_xor_sync(0xffffu, e, 1);
                se += __shfl_xor_sync(0xffffu, se, 2);
                size_t o = ((size_t)(b0 + gg) * S_ + tt) * 4 + c;
                outL[o] = lg;
                outP[o] = e / se;
            } else if (lane < 20) {
                int gg = lane - 16;
                ull acc = 0ull;
#pragma unroll
                for (int k2 = 0; k2 < 50; k2++)
                    FMA2(acc, *(const ull*)(sm + O_W2M + 2 * k2),
                         *(const ull*)(h1o + gg * 100 + 2 * k2), acc);
                outM[(size_t)(b0 + gg) * S_ + tt] = HADD(acc) + sm[O_B2M];
            }
        }
        __syncthreads();   // sync C

        // ======== stage 3: S3(t) feats ========
        if (tid < 200 && t < S_) {
            int f = tid >> 2, gg = tid & 3;
            ull acc = 0ull;
            const float* h1c = sm + O_H1 + (t & 1) * 400 + gg * 100;
#pragma unroll
            for (int j = 0; j < 25; j++) {
                ulonglong2 w = *(const ulonglong2*)(W2 + f * 100 + j * 4);
                ulonglong2 h = *(const ulonglong2*)(h1c + j * 4);
                FMA2(acc, w.x, h.x, acc);
                FMA2(acc, w.y, h.y, acc);
            }
            float feat = HADD(acc) + __ldg(b2 + f);
            outF[((size_t)(b0 + gg) * S_ + t) * 50 + f] = feat;
        }
    }
}

// ---------------------------------------------------------------------------

extern "C" void kernel_launch(void* const* d_in, const int* in_sizes, int n_in,
                              void* d_out, int out_size) {
    const int*   questions = (const int*)d_in[0];
    const int*   responses = (const int*)d_in[1];
    const float* qet       = (const float*)d_in[2];
    const float* Wv        = (const float*)d_in[3];
    const float* bv        = (const float*)d_in[4];
    const float* km        = (const float*)d_in[5];
    const float* ivm       = (const float*)d_in[6];
    const float* Wq        = (const float*)d_in[7];
    const float* bq        = (const float*)d_in[8];
    const float* Wk        = (const float*)d_in[9];
    const float* bk        = (const float*)d_in[10];
    const float* We        = (const float*)d_in[11];
    const float* be        = (const float*)d_in[12];
    const float* Wa        = (const float*)d_in[13];
    const float* ba        = (const float*)d_in[14];
    const float* W1        = (const float*)d_in[15];
    const float* b1        = (const float*)d_in[16];
    const float* W2        = (const float*)d_in[17];
    const float* b2        = (const float*)d_in[18];
    const float* Wo        = (const float*)d_in[19];
    const float* bo        = (const float*)d_in[20];

    float* out  = (float*)d_out;
    float* outF = out;
    float* outM = out + (size_t)512 * 500 * 50;
    float* outL = outM + (size_t)512 * 500;
    float* outP = outL + (size_t)512 * 500 * 4;

    const int smem_bytes = SMEM_F * 4;
    cudaFuncSetAttribute(akvmn_main, cudaFuncAttributeMaxDynamicSharedMemorySize,
                         smem_bytes);

    prepA<<<3534, 256>>>(Wv, bv, qet, W1, b1, km, Wk, bk, W2, b2, Wo, bo);
    prepB<<<1001, 64>>>(qet, Wq, bq);
    {
        dim3 grid(63, 7);
        prepC<<<grid, 256>>>(We, be, Wa, ba);
    }
    akvmn_main<<<512 / G, TPB, smem_bytes>>>(
        questions, responses, ivm, W1, W2, b2,
        outF, outM, outL, outP);
}

// round 7
// speedup vs baseline: 1.5140x; 1.5140x over previous
#include <cuda_runtime.h>
#include <math.h>

typedef unsigned long long ull;
constexpr int S_ = 500;

// ---------------- device scratch ----------------
__device__ float g_tk[2500];
__device__ float g_attn[1001 * 52];
__device__ float g_c1[1001 * 100];
__device__ float g_ve[4004 * 200];
__device__ float g_ea[(size_t)4004 * 400];
__device__ float g_wo2[400];
__device__ float g_bo2[4];
__device__ float g_w2m[100];
__device__ float g_b2m[1];
__device__ float g_h[(size_t)512 * 500 * 200];   // read vectors [b][t][200]

// ---------------- f32x2 helpers ----------------
#define FMA2(d, a, b, c) \
    asm("fma.rn.f32x2 %0, %1, %2, %3;" : "=l"(d) : "l"(a), "l"(b), "l"(c))
__device__ __forceinline__ ull PK(float x, float y) {
    ull u;
    asm("mov.b64 %0, {%1, %2};" : "=l"(u) : "r"(__float_as_uint(x)), "r"(__float_as_uint(y)));
    return u;
}
__device__ __forceinline__ float HADD(ull u) {
    unsigned lo, hi;
    asm("mov.b64 {%0, %1}, %2;" : "=r"(lo), "=r"(hi) : "l"(u));
    return __uint_as_float(lo) + __uint_as_float(hi);
}
__device__ __forceinline__ void cp16(float* dst, const float* src) {
    unsigned d = (unsigned)__cvta_generic_to_shared(dst);
    asm volatile("cp.async.ca.shared.global [%0], [%1], 16;\n" :: "r"(d), "l"(src));
}

// ---------------- prep kernels (unchanged from R5) ----------------
__global__ void prepA(const float* __restrict__ Wv, const float* __restrict__ bv,
                      const float* __restrict__ qet, const float* __restrict__ W1,
                      const float* __restrict__ b1,
                      const float* __restrict__ km, const float* __restrict__ Wk,
                      const float* __restrict__ bk,
                      const float* __restrict__ W2, const float* __restrict__ b2,
                      const float* __restrict__ Wo, const float* __restrict__ bo) {
    int b = blockIdx.x, tid = threadIdx.x;
    if (b < 3129) {
        int idx = b * 256 + tid;
        if (idx < 4004 * 200) {
            int i = idx / 200, v = idx % 200;
            int q = i >> 2, r = i & 3;
            float acc = bv[v];
            if (q > 0) {
#pragma unroll
                for (int c = 0; c < 4; c++) {
                    float w = 1.0f - fabsf((float)(c - r)) * (1.0f / 3.0f);
                    if (w > 0.0f) acc = fmaf(w, Wv[v * 4000 + c * 1000 + q - 1], acc);
                }
            }
            g_ve[idx] = acc;
        }
    } else if (b < 3521) {
        int idx = (b - 3129) * 256 + tid;
        if (idx < 1001 * 100) {
            int q = idx / 100, j = idx % 100;
            float a = b1[j];
            const float* w = W1 + j * 250 + 200;
            const float* e = qet + q * 50;
            for (int k = 0; k < 50; k++) a = fmaf(w[k], e[k], a);
            g_c1[idx] = a;
        }
    } else if (b < 3531) {
        int i = (b - 3521) * 256 + tid;
        if (i < 2500) {
            int m = i / 50, k = i % 50;
            float a = bk[m];
            for (int l = 0; l < 50; l++) a = fmaf(km[l * 50 + k], Wk[m * 50 + l], a);
            g_tk[i] = a;
        }
    } else {
        int i = (b - 3531) * 256 + tid;
        if (i < 400) {
            int c = i / 100, k = i % 100;
            float a = 0.f;
            for (int f = 0; f < 50; f++) a = fmaf(Wo[c * 50 + f], W2[f * 100 + k], a);
            g_wo2[i] = a;
        } else if (i < 500) {
            int k = i - 400;
            float a = 0.f;
            for (int f = 0; f < 50; f++) a += W2[f * 100 + k];
            g_w2m[k] = a * (1.f / 50.f);
        } else if (i < 504) {
            int c = i - 500;
            float a = bo[c];
            for (int f = 0; f < 50; f++) a = fmaf(Wo[c * 50 + f], b2[f], a);
            g_bo2[c] = a;
        } else if (i == 504) {
            float a = 0.f;
            for (int f = 0; f < 50; f++) a += b2[f];
            g_b2m[0] = a * (1.f / 50.f);
        }
    }
}

__global__ void prepB(const float* __restrict__ qet, const float* __restrict__ Wq,
                      const float* __restrict__ bq) {
    __shared__ float qe[50], qu[50], lg[50], red[2];
    int q = blockIdx.x, tid = threadIdx.x;
    if (tid < 50) qe[tid] = qet[q * 50 + tid];
    __syncthreads();
    if (tid < 50) {
        float a = bq[tid];
        for (int l = 0; l < 50; l++) a = fmaf(Wq[tid * 50 + l], qe[l], a);
        qu[tid] = tanhf(a);
    }
    __syncthreads();
    if (tid < 50) {
        float a = 0.f;
        for (int k = 0; k < 50; k++) a = fmaf(g_tk[tid * 50 + k], qu[k], a);
        lg[tid] = a;
    }
    __syncthreads();
    if (tid == 0) {
        float mx = -1e30f;
        for (int m = 0; m < 50; m++) mx = fmaxf(mx, lg[m]);
        float s = 0.f;
        for (int m = 0; m < 50; m++) s += expf(lg[m] - mx);
        red[0] = mx; red[1] = 1.f / s;
    }
    __syncthreads();
    if (tid < 52) g_attn[q * 52 + tid] = (tid < 50) ? expf(lg[tid] - red[0]) * red[1] : 0.f;
}

__global__ void prepC(const float* __restrict__ We, const float* __restrict__ be,
                      const float* __restrict__ Wa, const float* __restrict__ ba) {
    __shared__ float As[16][64];
    __shared__ float Bs[16][64];
    int i0 = blockIdx.x * 64, j0 = blockIdx.y * 64;
    int tid = threadIdx.x;
    int ty = tid >> 4, tx = tid & 15;
    float acc[4][4] = {};
    for (int kb = 0; kb < 200; kb += 16) {
        for (int l = tid; l < 1024; l += 256) {
            int r = l >> 4, c = l & 15;
            int gi = i0 + r, gk = kb + c;
            As[c][r] = (gi < 4004 && gk < 200) ? g_ve[gi * 200 + gk] : 0.f;
            int gj = j0 + r;
            float bval = 0.f;
            if (gj < 400 && gk < 200)
                bval = (gj < 200) ? We[gj * 200 + gk] : Wa[(gj - 200) * 200 + gk];
            Bs[c][r] = bval;
        }
        __syncthreads();
#pragma unroll
        for (int k = 0; k < 16; k++) {
            float a[4], b[4];
#pragma unroll
            for (int u = 0; u < 4; u++) a[u] = As[k][ty * 4 + u];
#pragma unroll
            for (int u = 0; u < 4; u++) b[u] = Bs[k][tx * 4 + u];
#pragma unroll
            for (int u = 0; u < 4; u++)
#pragma unroll
                for (int v = 0; v < 4; v++) acc[u][v] = fmaf(a[u], b[v], acc[u][v]);
        }
        __syncthreads();
    }
#pragma unroll
    for (int u = 0; u < 4; u++) {
        int gi = i0 + ty * 4 + u;
        if (gi >= 4004) break;
#pragma unroll
        for (int v = 0; v < 4; v++) {
            int gj = j0 + tx * 4 + v;
            if (gj >= 400) continue;
            float x = acc[u][v] + ((gj < 200) ? be[gj] : ba[gj - 200]);
            g_ea[(size_t)gi * 400 + gj] = (gj < 200) ? (1.0f / (1.0f + expf(-x))) : tanhf(x);
        }
    }
}

// ================= Phase 1: Vm recurrence only =================
#define TPB1 224
constexpr int G1 = 2;
// smem: [2 bufs x 904: ea(800) at(104)] [qs 1000] [rs 1000]
constexpr int P1_QS = 1808;
constexpr int P1_RS = 2808;
constexpr int P1_SMF = 3808;

#define S1_STEP(X, RACC) do {                   \
        ull at2 = PK(av, av); ull tt;           \
        FMA2(RACC, at2, (X), RACC);             \
        FMA2(tt, en, (X), ad);                  \
        FMA2((X), at2, tt, (X));                \
    } while (0)

__device__ __forceinline__ void p1_prefetch(float* buf, const int* qs, const int* rs,
                                            int t1, int i0) {
    for (int i = i0; i < 226; i += TPB1 - 200) {
        if (i < 200) {
            int g = i / 100, j = i % 100;
            int q = qs[g * S_ + t1], r = rs[g * S_ + t1];
            cp16(buf + g * 400 + j * 4, g_ea + (size_t)(q * 4 + r) * 400 + j * 4);
        } else {
            int k = i - 200, g = k / 13, j = k % 13;
            cp16(buf + 800 + g * 52 + j * 4, g_attn + qs[g * S_ + t1] * 52 + j * 4);
        }
    }
}

__global__ void __launch_bounds__(TPB1, 2)
phase1(const int* __restrict__ questions, const int* __restrict__ responses,
       const float* __restrict__ ivm) {
    __shared__ float sm[P1_SMF];
    int* qs = (int*)(sm + P1_QS);
    int* rs = (int*)(sm + P1_RS);
    const int tid = threadIdx.x;
    const int b0 = blockIdx.x * G1;

    for (int i = tid; i < G1 * S_; i += TPB1) {
        qs[i] = questions[b0 * S_ + i];
        rs[i] = responses[b0 * S_ + i];
    }

    const int g = (tid < 200) ? tid / 100 : 0;
    const int p = (tid < 200) ? tid % 100 : 0;
    ull vm[50];
    if (tid < 200) {
#pragma unroll
        for (int m = 0; m < 50; m++) vm[m] = *(const ull*)(ivm + m * 200 + 2 * p);
    }
    __syncthreads();
    if (tid >= 200) {
        p1_prefetch(sm, qs, rs, 0, tid - 200);
        asm volatile("cp.async.commit_group;\n" ::: "memory");
    }

    size_t hbase = (size_t)(b0 + g) * (S_ * 200) + 2 * p;

    for (int t = 0; t < S_; t++) {
        if (tid >= 200)
            asm volatile("cp.async.wait_group 0;\n" ::: "memory");
        __syncthreads();

        if (tid < 200) {
            const float* tc = sm + (t & 1) * 904;
            float2 e2 = *(const float2*)(tc + g * 400 + 2 * p);
            float2 a2 = *(const float2*)(tc + g * 400 + 200 + 2 * p);
            ull en = PK(-e2.x, -e2.y), ad = PK(a2.x, a2.y);
            const float* at = tc + 800 + g * 52;
            ull r2a = 0ull, r2b = 0ull;
#pragma unroll
            for (int c = 0; c < 12; c++) {
                float4 a4 = *(const float4*)(at + c * 4);
                {   float av = a4.x; S1_STEP(vm[c * 4 + 0], r2a); }
                {   float av = a4.y; S1_STEP(vm[c * 4 + 1], r2b); }
                {   float av = a4.z; S1_STEP(vm[c * 4 + 2], r2a); }
                {   float av = a4.w; S1_STEP(vm[c * 4 + 3], r2b); }
            }
            {
                float2 alast = *(const float2*)(at + 48);
                {   float av = alast.x; S1_STEP(vm[48], r2a); }
                {   float av = alast.y; S1_STEP(vm[49], r2b); }
            }
            ull one2 = PK(1.0f, 1.0f), r2;
            FMA2(r2, r2b, one2, r2a);
            *(ull*)(g_h + hbase + (size_t)t * 200) = r2;
        } else {
            if (t + 1 < S_)
                p1_prefetch(sm + ((t + 1) & 1) * 904, qs, rs, t + 1, tid - 200);
            asm volatile("cp.async.commit_group;\n" ::: "memory");
        }
    }
}

// ================= Phase 2: batched MLP over all (b,t) =================
#define TPB2 256
constexpr int HSTR = 204;    // padded h row stride (floats)
constexpr int H1STR = 102;   // padded h1 row stride
constexpr int O2_H = 0;                       // 64 x 204 = 13056
constexpr int O2_H1 = 13056;                  // 64 x 102 = 6528
constexpr int O2_QN = 19584;                  // 64 int
constexpr int P2_SMF = 19648;                 // 78,592 B

__global__ void __launch_bounds__(TPB2, 2)
phase2(const int* __restrict__ questions, const float* __restrict__ W1,
       const float* __restrict__ W2, const float* __restrict__ b2,
       float* __restrict__ outF, float* __restrict__ outM,
       float* __restrict__ outL, float* __restrict__ outP) {
    extern __shared__ float s2[];
    const int tid = threadIdx.x;
    const int n0 = blockIdx.x * 64;
    int* qn = (int*)(s2 + O2_QN);

    // ---- stage A: load 64 h rows + question ids ----
    for (int i = tid; i < 3200; i += TPB2) {
        int r = i / 50, c = i % 50;
        cp16(s2 + O2_H + r * HSTR + c * 4, g_h + (size_t)(n0 + r) * 200 + c * 4);
    }
    if (tid < 64) qn[tid] = questions[n0 + tid];
    asm volatile("cp.async.commit_group;\n" ::: "memory");
    asm volatile("cp.async.wait_group 0;\n" ::: "memory");
    __syncthreads();

    // ---- stage B: h1 = relu(W1[:, :200] @ h + c1[q]) ----
    // 200 threads: jg = tid/8 (25 groups of 4 j), rg = tid%8; rows owned strided: r = rg + 8i
    if (tid < 200) {
        int jg = tid / 8, rg = tid % 8;
        int j0 = jg * 4;
        ull acc[4][8] = {};
        for (int k = 0; k < 200; k += 2) {
            ull h[8];
#pragma unroll
            for (int i = 0; i < 8; i++)
                h[i] = *(const ull*)(s2 + O2_H + (rg + 8 * i) * HSTR + k);
#pragma unroll
            for (int j = 0; j < 4; j++) {
                ull w = *(const ull*)(W1 + (j0 + j) * 250 + k);
#pragma unroll
                for (int i = 0; i < 8; i++) FMA2(acc[j][i], w, h[i], acc[j][i]);
            }
        }
#pragma unroll
        for (int j = 0; j < 4; j++)
#pragma unroll
            for (int i = 0; i < 8; i++) {
                int row = rg + 8 * i;
                float v = HADD(acc[j][i]) + g_c1[qn[row] * 100 + j0 + j];
                s2[O2_H1 + row * H1STR + j0 + j] = fmaxf(v, 0.f);
            }
    }
    __syncthreads();

    // ---- stage C: feats, logits, probs, mastery ----
    // feats: 3200 tasks (f = task/64, row = task%64)
    for (int task = tid; task < 3200; task += TPB2) {
        int f = task >> 6, row = task & 63;
        ull acc = 0ull;
        const float* h1r = s2 + O2_H1 + row * H1STR;
#pragma unroll
        for (int k2 = 0; k2 < 50; k2++)
            FMA2(acc, *(const ull*)(W2 + f * 100 + 2 * k2),
                 *(const ull*)(h1r + 2 * k2), acc);
        outF[(size_t)(n0 + row) * 50 + f] = HADD(acc) + __ldg(b2 + f);
    }
    // logits + probs: 256 tasks (row = tid/4, c = tid%4)
    {
        int row = tid >> 2, c = tid & 3;
        ull acc = 0ull;
        const float* h1r = s2 + O2_H1 + row * H1STR;
#pragma unroll
        for (int k2 = 0; k2 < 50; k2++)
            FMA2(acc, *(const ull*)(g_wo2 + c * 100 + 2 * k2),
                 *(const ull*)(h1r + 2 * k2), acc);
        float lg = HADD(acc) + g_bo2[c];
        float mx = fmaxf(lg, __shfl_xor_sync(0xffffffffu, lg, 1));
        mx = fmaxf(mx, __shfl_xor_sync(0xffffffffu, mx, 2));
        float e = expf(lg - mx);
        float se = e + __shfl_xor_sync(0xffffffffu, e, 1);
        se += __shfl_xor_sync(0xffffffffu, se, 2);
        size_t o = (size_t)(n0 + row) * 4 + c;
        outL[o] = lg;
        outP[o] = e / se;
    }
    // mastery: 64 tasks
    if (tid < 64) {
        ull acc = 0ull;
        const float* h1r = s2 + O2_H1 + tid * H1STR;
#pragma unroll
        for (int k2 = 0; k2 < 50; k2++)
            FMA2(acc, *(const ull*)(g_w2m + 2 * k2), *(const ull*)(h1r + 2 * k2), acc);
        outM[n0 + tid] = HADD(acc) + g_b2m[0];
    }
}

// ---------------------------------------------------------------------------

extern "C" void kernel_launch(void* const* d_in, const int* in_sizes, int n_in,
                              void* d_out, int out_size) {
    const int*   questions = (const int*)d_in[0];
    const int*   responses = (const int*)d_in[1];
    const float* qet       = (const float*)d_in[2];
    const float* Wv        = (const float*)d_in[3];
    const float* bv        = (const float*)d_in[4];
    const float* km        = (const float*)d_in[5];
    const float* ivm       = (const float*)d_in[6];
    const float* Wq        = (const float*)d_in[7];
    const float* bq        = (const float*)d_in[8];
    const float* Wk        = (const float*)d_in[9];
    const float* bk        = (const float*)d_in[10];
    const float* We        = (const float*)d_in[11];
    const float* be        = (const float*)d_in[12];
    const float* Wa        = (const float*)d_in[13];
    const float* ba        = (const float*)d_in[14];
    const float* W1        = (const float*)d_in[15];
    const float* b1        = (const float*)d_in[16];
    const float* W2        = (const float*)d_in[17];
    const float* b2        = (const float*)d_in[18];
    const float* Wo        = (const float*)d_in[19];
    const float* bo        = (const float*)d_in[20];

    float* out  = (float*)d_out;
    float* outF = out;
    float* outM = out + (size_t)512 * 500 * 50;
    float* outL = outM + (size_t)512 * 500;
    float* outP = outL + (size_t)512 * 500 * 4;

    cudaFuncSetAttribute(phase2, cudaFuncAttributeMaxDynamicSharedMemorySize,
                         P2_SMF * 4);

    prepA<<<3534, 256>>>(Wv, bv, qet, W1, b1, km, Wk, bk, W2, b2, Wo, bo);
    prepB<<<1001, 64>>>(qet, Wq, bq);
    {
        dim3 grid(63, 7);
        prepC<<<grid, 256>>>(We, be, Wa, ba);
    }
    phase1<<<512 / G1, TPB1>>>(questions, responses, ivm);
    phase2<<<4000, TPB2, P2_SMF * 4>>>(questions, W1, W2, b2,
                                       outF, outM, outL, outP);
}